// round 16
// baseline (speedup 1.0000x reference)
#include <cuda_runtime.h>

#define N 8192
#define ROWS_PER_BLK 256
#define COLS_PER_BLK 256
#define CB 32     /* column tiles: 8192/256 */
#define RB 32     /* row tiles:    8192/256 */
#define THREADS 256
#define BAND_LAST 62   /* old value seen by the 63rd (last) arrival */

// Scratch (no device allocation allowed -> __device__ globals)
__device__ float g_rowpart[CB * N];     // [cb][row]  partial row sums (1 MiB)
__device__ float g_colpart[RB * N];     // [rb][col]  partial col sums (1 MiB)
__device__ float g_bandsum[32];
__device__ int   g_band_cnt[32];        // zero-init; self-resetting
__device__ int   g_cnt_final;           // zero-init; self-resetting

// ---------------------------------------------------------------------------
// Band finisher (NOINLINE: keeps the hot loop's scheduling region clean —
// this is the controlled retry of R7). Folds band g's 64 KB of partials:
// thread t owns column/row g*256+t. Fixed-order sums -> deterministic.
// The globally-last finisher folds the 32 band sums -> out, resets counters.
// ---------------------------------------------------------------------------
__device__ __noinline__ void finish_band(int g, float* __restrict__ out)
{
    const int t = threadIdx.x;
    __threadfence();   // acquire: producers' partials visible

    const int i = g * 256 + t;   // global column / row index

    float cs = 0.f;
    #pragma unroll 8
    for (int rb = 0; rb < RB; ++rb) cs += g_colpart[rb * N + i];

    float rs = 0.f;
    #pragma unroll 8
    for (int cb = 0; cb < CB; ++cb) rs += g_rowpart[cb * N + i];

    float v = fabsf(rs - cs);
    v += __shfl_xor_sync(0xffffffffu, v, 16);
    v += __shfl_xor_sync(0xffffffffu, v, 8);
    v += __shfl_xor_sync(0xffffffffu, v, 4);
    v += __shfl_xor_sync(0xffffffffu, v, 2);
    v += __shfl_xor_sync(0xffffffffu, v, 1);

    __shared__ float sw[8];
    __shared__ int s_fin;
    if ((t & 31) == 0) sw[t >> 5] = v;
    __syncthreads();

    if (t == 0) {
        float w = ((sw[0] + sw[1]) + (sw[2] + sw[3]))
                + ((sw[4] + sw[5]) + (sw[6] + sw[7]));
        g_bandsum[g] = w;
        __threadfence();
        s_fin = (atomicAdd(&g_cnt_final, 1) == 31);
    }
    __syncthreads();

    if (s_fin) {
        __threadfence();
        if (t < 32) {
            float v2 = g_bandsum[t];
            v2 += __shfl_xor_sync(0xffffffffu, v2, 16);
            v2 += __shfl_xor_sync(0xffffffffu, v2, 8);
            v2 += __shfl_xor_sync(0xffffffffu, v2, 4);
            v2 += __shfl_xor_sync(0xffffffffu, v2, 2);
            v2 += __shfl_xor_sync(0xffffffffu, v2, 1);
            if (t == 0) {
                out[0] = v2;
                g_cnt_final = 0;                       // reset for replay
                #pragma unroll
                for (int k = 0; k < 32; ++k) g_band_cnt[k] = 0;
            }
        }
    }
    __syncthreads();
}

// ---------------------------------------------------------------------------
// Single fused kernel: one block per 256x256 tile -> 1024 blocks. Proven
// streaming loop; partials published with plain stores; last arriver per
// band runs the (noinline) finisher.
// ---------------------------------------------------------------------------
__global__ void __launch_bounds__(THREADS)
tile_kernel(const float* __restrict__ flow, float* __restrict__ out)
{
    const int cb   = blockIdx.x;          // 0..31
    const int rb   = blockIdx.y;          // 0..31
    const int t    = threadIdx.x;         // 0..255
    const int lane = t & 31;
    const int fc   = t & 63;              // float4-col within tile
    const int rsub = t >> 6;              // 0..3
    const int half = (t >> 5) & 1;
    const int row0 = rb * ROWS_PER_BLK;
    const int col0 = cb * COLS_PER_BLK;

    __shared__ float  s_row[ROWS_PER_BLK][8];     // 8 KB
    __shared__ float4 s_cpart[4][64];             // 4 KB

    float4 c0 = make_float4(0.f, 0.f, 0.f, 0.f);

    const float4* base = reinterpret_cast<const float4*>(flow)
                         + (size_t)row0 * (N / 4) + (col0 / 4) + fc;

    #pragma unroll 4
    for (int k = 0; k < ROWS_PER_BLK / 4; ++k) {
        const int r = k * 4 + rsub;
        float4 a = __ldcs(base + (size_t)r * (N / 4));   // streaming

        c0.x += a.x; c0.y += a.y; c0.z += a.z; c0.w += a.w;

        float s = (a.x + a.y) + (a.z + a.w);
        s += __shfl_xor_sync(0xffffffffu, s, 16);
        s += __shfl_xor_sync(0xffffffffu, s, 8);
        s += __shfl_xor_sync(0xffffffffu, s, 4);
        if (lane < 4) s_row[r][half * 4 + lane] = s;
    }

    s_cpart[rsub][fc] = c0;
    __syncthreads();

    // Column fold: threads 0..63 fold the 4 rsub partials per float4-col.
    if (t < 64) {
        float4 a0 = s_cpart[0][t], a1 = s_cpart[1][t];
        float4 a2 = s_cpart[2][t], a3 = s_cpart[3][t];
        float4 c;
        c.x = (a0.x + a1.x) + (a2.x + a3.x);
        c.y = (a0.y + a1.y) + (a2.y + a3.y);
        c.z = (a0.z + a1.z) + (a2.z + a3.z);
        c.w = (a0.w + a1.w) + (a2.w + a3.w);
        reinterpret_cast<float4*>(g_colpart + (size_t)rb * N + col0)[t] = c;
    }

    // Row fold: thread r folds its row's 8 partials (fixed order).
    {
        const float* p = s_row[t];
        float s = ((p[0] + p[1]) + (p[2] + p[3]))
                + ((p[4] + p[5]) + (p[6] + p[7]));
        g_rowpart[cb * N + row0 + t] = s;
    }

    // Publish, then elect last-arriver per band (63 arrivals per band).
    __syncthreads();
    __threadfence();
    __shared__ int s_f1, s_f2;
    if (t == 0) {
        s_f1 = (atomicAdd(&g_band_cnt[cb], 1) == BAND_LAST);
        s_f2 = (rb != cb) ? (atomicAdd(&g_band_cnt[rb], 1) == BAND_LAST) : 0;
    }
    __syncthreads();

    if (s_f1) finish_band(cb, out);
    if (s_f2) finish_band(rb, out);
}

extern "C" void kernel_launch(void* const* d_in, const int* in_sizes, int n_in,
                              void* d_out, int out_size)
{
    (void)in_sizes; (void)n_in; (void)out_size;
    const float* flow = (const float*)d_in[0];
    float* out = (float*)d_out;

    tile_kernel<<<dim3(CB, RB), THREADS>>>(flow, out);
}

// round 17
// speedup vs baseline: 1.4362x; 1.4362x over previous
#include <cuda_runtime.h>

#define N 8192
#define ROWS_PER_BLK 256
#define COLS_PER_BLK 256
#define CB 32     /* column tiles: 8192/256 */
#define RB 32     /* row tiles:    8192/256 */
#define THREADS 256
#define EBLK 128  /* epilogue blocks */

// Scratch (no device allocation allowed -> __device__ globals)
__device__ float g_rowpart[CB * N];     // [cb][row]  partial row sums (1 MiB)
__device__ float g_colpart[RB * N];     // [rb][col]  partial col sums (1 MiB)
__device__ float g_blocksum[EBLK];
__device__ int   g_cnt_final;           // zero-init; self-resetting

// ---------------------------------------------------------------------------
// Pass 1: one block per 256x256 tile -> 1024 blocks (proven ~43.5us @ 78%
// of HBM spec). Streaming single read of the 256 MiB matrix. Per iteration:
// 1 LDG.128 -> register col accum + 3-shuffle row partial. NO epilogue code
// in this kernel (any finisher costs registers -> occupancy -> bandwidth).
// ---------------------------------------------------------------------------
__global__ void __launch_bounds__(THREADS)
tile_kernel(const float* __restrict__ flow)
{
    const int cb   = blockIdx.x;          // 0..31
    const int rb   = blockIdx.y;          // 0..31
    const int t    = threadIdx.x;         // 0..255
    const int lane = t & 31;
    const int fc   = t & 63;              // float4-col within tile
    const int rsub = t >> 6;              // 0..3
    const int half = (t >> 5) & 1;
    const int row0 = rb * ROWS_PER_BLK;
    const int col0 = cb * COLS_PER_BLK;

    __shared__ float  s_row[ROWS_PER_BLK][8];     // 8 KB
    __shared__ float4 s_cpart[4][64];             // 4 KB

    float4 c0 = make_float4(0.f, 0.f, 0.f, 0.f);

    const float4* base = reinterpret_cast<const float4*>(flow)
                         + (size_t)row0 * (N / 4) + (col0 / 4) + fc;

    #pragma unroll 4
    for (int k = 0; k < ROWS_PER_BLK / 4; ++k) {
        const int r = k * 4 + rsub;
        float4 a = __ldcs(base + (size_t)r * (N / 4));   // streaming

        c0.x += a.x; c0.y += a.y; c0.z += a.z; c0.w += a.w;

        // partial row reduce: 32 lanes -> 4 partials (3 shuffles)
        float s = (a.x + a.y) + (a.z + a.w);
        s += __shfl_xor_sync(0xffffffffu, s, 16);
        s += __shfl_xor_sync(0xffffffffu, s, 8);
        s += __shfl_xor_sync(0xffffffffu, s, 4);
        if (lane < 4) s_row[r][half * 4 + lane] = s;
    }

    s_cpart[rsub][fc] = c0;
    __syncthreads();

    // Column fold: threads 0..63 fold the 4 rsub partials per float4-col.
    if (t < 64) {
        float4 a0 = s_cpart[0][t], a1 = s_cpart[1][t];
        float4 a2 = s_cpart[2][t], a3 = s_cpart[3][t];
        float4 c;
        c.x = (a0.x + a1.x) + (a2.x + a3.x);
        c.y = (a0.y + a1.y) + (a2.y + a3.y);
        c.z = (a0.z + a1.z) + (a2.z + a3.z);
        c.w = (a0.w + a1.w) + (a2.w + a3.w);
        reinterpret_cast<float4*>(g_colpart + (size_t)rb * N + col0)[t] = c;
    }

    // Row fold: thread r folds its row's 8 partials (fixed order).
    {
        const float* p = s_row[t];
        float s = ((p[0] + p[1]) + (p[2] + p[3]))
                + ((p[4] + p[5]) + (p[6] + p[7]));
        g_rowpart[cb * N + row0 + t] = s;
    }
}

// ---------------------------------------------------------------------------
// Pass 2 (PDL epilogue, 128 blocks x 256 threads): block owns 64 columns
// (16 float4-cols). 16 subs: subs 0..7 fold colpart (4 independent float4
// loads each), subs 8..15 fold rowpart. 2 MiB covered in exactly one pass.
// smem fold -> |rowsum - colsum| -> warp reduce -> counter-gated finish.
// Fixed-order FP + integer atomics -> bitwise deterministic; self-resetting.
// ---------------------------------------------------------------------------
__global__ void __launch_bounds__(256)
epilogue_kernel(float* __restrict__ out)
{
    const int t   = threadIdx.x;            // 0..255
    const int fcl = t & 15;                 // float4-col within block
    const int sub = t >> 4;                 // 0..15
    const int fc  = blockIdx.x * 16 + fcl;  // global float4-col

    cudaGridDependencySynchronize();        // wait for tile kernel's writes

    const float4* cp = reinterpret_cast<const float4*>(g_colpart);
    const float4* rp = reinterpret_cast<const float4*>(g_rowpart);

    float4 acc = make_float4(0.f, 0.f, 0.f, 0.f);
    if (sub < 8) {
        #pragma unroll
        for (int j = 0; j < 4; ++j) {
            float4 a = cp[(size_t)(sub * 4 + j) * (N / 4) + fc];
            acc.x += a.x; acc.y += a.y; acc.z += a.z; acc.w += a.w;
        }
    } else {
        #pragma unroll
        for (int j = 0; j < 4; ++j) {
            float4 a = rp[(size_t)((sub - 8) * 4 + j) * (N / 4) + fc];
            acc.x += a.x; acc.y += a.y; acc.z += a.z; acc.w += a.w;
        }
    }

    __shared__ float4 s_part[16][17];       // [sub][fcl] padded
    s_part[sub][fcl] = acc;
    __syncthreads();

    float v = 0.f;
    if (t < 16) {
        float4 cs = make_float4(0.f, 0.f, 0.f, 0.f);
        float4 rs = make_float4(0.f, 0.f, 0.f, 0.f);
        #pragma unroll
        for (int s2 = 0; s2 < 8; ++s2) {
            float4 a = s_part[s2][t];
            cs.x += a.x; cs.y += a.y; cs.z += a.z; cs.w += a.w;
            float4 b = s_part[s2 + 8][t];
            rs.x += b.x; rs.y += b.y; rs.z += b.z; rs.w += b.w;
        }
        v = (fabsf(rs.x - cs.x) + fabsf(rs.y - cs.y))
          + (fabsf(rs.z - cs.z) + fabsf(rs.w - cs.w));
    }

    if (t < 32) {
        v += __shfl_xor_sync(0xffffffffu, v, 8);
        v += __shfl_xor_sync(0xffffffffu, v, 4);
        v += __shfl_xor_sync(0xffffffffu, v, 2);
        v += __shfl_xor_sync(0xffffffffu, v, 1);
        if (t == 0) g_blocksum[blockIdx.x] = v;
    }

    // gate: globally-last block folds the 128 block sums
    __threadfence();
    __syncthreads();
    __shared__ int s_fin;
    if (t == 0) s_fin = (atomicAdd(&g_cnt_final, 1) == EBLK - 1);
    __syncthreads();
    if (!s_fin) return;
    __threadfence();

    float w = (t < EBLK) ? g_blocksum[t] : 0.f;
    w += __shfl_xor_sync(0xffffffffu, w, 16);
    w += __shfl_xor_sync(0xffffffffu, w, 8);
    w += __shfl_xor_sync(0xffffffffu, w, 4);
    w += __shfl_xor_sync(0xffffffffu, w, 2);
    w += __shfl_xor_sync(0xffffffffu, w, 1);

    __shared__ float sw[8];
    if ((t & 31) == 0) sw[t >> 5] = w;
    __syncthreads();

    if (t == 0) {
        float w2 = ((sw[0] + sw[1]) + (sw[2] + sw[3]))
                 + ((sw[4] + sw[5]) + (sw[6] + sw[7]));
        out[0] = w2;
        g_cnt_final = 0;   // reset for next graph replay
    }
}

extern "C" void kernel_launch(void* const* d_in, const int* in_sizes, int n_in,
                              void* d_out, int out_size)
{
    (void)in_sizes; (void)n_in; (void)out_size;
    const float* flow = (const float*)d_in[0];
    float* out = (float*)d_out;

    tile_kernel<<<dim3(CB, RB), THREADS>>>(flow);

    // Epilogue with Programmatic Dependent Launch (proven capturable).
    cudaLaunchConfig_t cfg = {};
    cfg.gridDim  = dim3(EBLK, 1, 1);
    cfg.blockDim = dim3(256, 1, 1);
    cudaLaunchAttribute attr[1];
    attr[0].id = cudaLaunchAttributeProgrammaticStreamSerialization;
    attr[0].val.programmaticStreamSerializationAllowed = 1;
    cfg.attrs = attr;
    cfg.numAttrs = 1;
    cudaLaunchKernelEx(&cfg, epilogue_kernel, out);
}